// round 4
// baseline (speedup 1.0000x reference)
#include <cuda_runtime.h>

#define Bdim 2
#define Lq 2048
#define Hdim 1024
#define NH 16
#define HD 64
#define MROWS (Bdim * Lq)   // 4096

// ---------------- scratch (static device arrays; no allocation) --------------
__device__ float g_Q[(size_t)Bdim * NH * Lq * HD];   // [b,h,l,d]
__device__ float g_K[(size_t)Bdim * NH * Lq * HD];
__device__ float g_V[(size_t)Bdim * NH * Lq * HD];
__device__ float g_ATT[(size_t)MROWS * Hdim];        // [b*l, h*64+d]
__device__ float g_O[(size_t)MROWS * Hdim];          // pre-LN projection

// ---------------- 128x128x16 SGEMM, 8x8 micro-tile ---------------------------
#define TBM 128
#define TBN 128
#define TBK 16

// which: 0->g_Q 1->g_K 2->g_V (head-split layout), 3: A=g_ATT, dst=g_O (plain)
__global__ __launch_bounds__(256) void gemm_k(const float* __restrict__ A,
                                              const float* __restrict__ W,
                                              const float* __restrict__ bias,
                                              int which)
{
    __shared__ float As[TBK][TBM];
    __shared__ float Bs[TBK][TBN];

    const float* __restrict__ Ap = (which == 3) ? g_ATT : A;
    float* dst;
    if (which == 0) dst = g_Q;
    else if (which == 1) dst = g_K;
    else if (which == 2) dst = g_V;
    else dst = g_O;

    const int tid = threadIdx.x;
    const int tx = tid & 15, ty = tid >> 4;
    const int row0 = blockIdx.y * TBM;
    const int col0 = blockIdx.x * TBN;

    float acc[8][8];
#pragma unroll
    for (int i = 0; i < 8; i++)
#pragma unroll
        for (int j = 0; j < 8; j++) acc[i][j] = 0.f;

    for (int kt = 0; kt < Hdim; kt += TBK) {
        // A tile 128x16 -> As[k][m] (transposed)
#pragma unroll
        for (int i = 0; i < 2; i++) {
            int e = tid * 4 + i * 1024;
            int m = e >> 4, k = e & 15;
            float4 v = *(const float4*)(Ap + (size_t)(row0 + m) * Hdim + kt + k);
            As[k + 0][m] = v.x; As[k + 1][m] = v.y;
            As[k + 2][m] = v.z; As[k + 3][m] = v.w;
        }
        // B tile 16x128 -> Bs[k][n]
#pragma unroll
        for (int i = 0; i < 2; i++) {
            int e = tid * 4 + i * 1024;
            int k = e >> 7, n = e & 127;
            *(float4*)(&Bs[k][n]) =
                *(const float4*)(W + (size_t)(kt + k) * Hdim + col0 + n);
        }
        __syncthreads();

#pragma unroll
        for (int k = 0; k < TBK; k++) {
            float a[8], b[8];
            *(float4*)(a)     = *(const float4*)(&As[k][ty * 8]);
            *(float4*)(a + 4) = *(const float4*)(&As[k][ty * 8 + 4]);
            *(float4*)(b)     = *(const float4*)(&Bs[k][tx * 8]);
            *(float4*)(b + 4) = *(const float4*)(&Bs[k][tx * 8 + 4]);
#pragma unroll
            for (int i = 0; i < 8; i++)
#pragma unroll
                for (int j = 0; j < 8; j++) acc[i][j] += a[i] * b[j];
        }
        __syncthreads();
    }

#pragma unroll
    for (int i = 0; i < 8; i++) {
        int m = row0 + ty * 8 + i;
        int bb = m >> 11;            // / Lq
        int l  = m & (Lq - 1);
#pragma unroll
        for (int j = 0; j < 8; j++) {
            int c = col0 + tx * 8 + j;
            float v = acc[i][j] + bias[c];
            if (which < 3) {
                int h = c >> 6, d = c & 63;
                dst[(((size_t)(bb * NH + h)) * Lq + l) * HD + d] = v;
            } else {
                dst[(size_t)m * Hdim + c] = v;
            }
        }
    }
}

// ---------------- flash attention (keys = V, values = K) ---------------------
// energies = Q @ V^T / 4 + mask; attended = softmax(energies) @ K
#define QB 128
#define KB 64
#define ATTN_SMEM_FLOATS (QB * 65 + KB * 65 + KB * 64 + QB * 65 + QB + KB)
#define ATTN_SMEM_BYTES  (ATTN_SMEM_FLOATS * 4)

__global__ __launch_bounds__(256) void attn_k(const float* __restrict__ mask)
{
    extern __shared__ float sm[];
    float* Qs  = sm;                    // [QB][65]
    float* Ks  = Qs + QB * 65;          // [KB][65]   (rows of V = "keys")
    float* Vs  = Ks + KB * 65;          // [KB][64]   (rows of K = "values")
    float* Ps  = Vs + KB * 64;          // [QB][65]   scores / probs
    float* fac = Ps + QB * 65;          // [QB]
    float* msk = fac + QB;              // [KB]

    const int tid = threadIdx.x;
    const int tx = tid & 15, ty = tid >> 4;
    const int q0 = blockIdx.x * QB;
    const int h  = blockIdx.y;
    const int b  = blockIdx.z;
    const size_t bh = (size_t)(b * NH + h);
    const float* __restrict__ Qg = g_Q + bh * Lq * HD;
    const float* __restrict__ Kg = g_V + bh * Lq * HD;   // keys are V
    const float* __restrict__ Vg = g_K + bh * Lq * HD;   // values are K

    // load Q tile [QB][64] (padded rows)
#pragma unroll
    for (int i = 0; i < (QB * 64) / 256; i++) {
        int e = i * 256 + tid;
        int q = e >> 6, d = e & 63;
        Qs[q * 65 + d] = Qg[(size_t)(q0 + q) * HD + d];
    }

    const int srow = tid >> 1;
    const int sseg = (tid & 1) * 32;
    float mprev = -1e30f, lsum = 0.f;
    float acc[8][4];
#pragma unroll
    for (int i = 0; i < 8; i++)
#pragma unroll
        for (int j = 0; j < 4; j++) acc[i][j] = 0.f;

    for (int kb = 0; kb < Lq / KB; kb++) {
        __syncthreads();   // Ks/Vs safe to overwrite (prev PV reads done)
        const int k0 = kb * KB;
#pragma unroll
        for (int i = 0; i < (KB * 64) / 256; i++) {
            int e = i * 256 + tid;
            int kk = e >> 6, d = e & 63;
            Ks[kk * 65 + d] = Kg[(size_t)(k0 + kk) * HD + d];
            Vs[kk * 64 + d] = Vg[(size_t)(k0 + kk) * HD + d];
        }
        if (tid < KB) msk[tid] = mask[b * Lq + k0 + tid];
        __syncthreads();

        // S[q][kk] : q = ty*8+i, kk = tx*4+j
        float s[8][4];
#pragma unroll
        for (int i = 0; i < 8; i++)
#pragma unroll
            for (int j = 0; j < 4; j++) s[i][j] = 0.f;

#pragma unroll 4
        for (int d = 0; d < 64; d++) {
            float a[8], bb[4];
#pragma unroll
            for (int i = 0; i < 8; i++) a[i] = Qs[(ty * 8 + i) * 65 + d];
#pragma unroll
            for (int j = 0; j < 4; j++) bb[j] = Ks[(tx * 4 + j) * 65 + d];
#pragma unroll
            for (int i = 0; i < 8; i++)
#pragma unroll
                for (int j = 0; j < 4; j++) s[i][j] += a[i] * bb[j];
        }
#pragma unroll
        for (int i = 0; i < 8; i++)
#pragma unroll
            for (int j = 0; j < 4; j++)
                Ps[(ty * 8 + i) * 65 + tx * 4 + j] = s[i][j] * 0.25f + msk[tx * 4 + j];
        __syncthreads();

        // row max (both threads of a row compute identical value)
        float mnew = mprev;
#pragma unroll 8
        for (int c = 0; c < 64; c++) mnew = fmaxf(mnew, Ps[srow * 65 + c]);
        float f = __expf(mprev - mnew);
        if (sseg == 0) fac[srow] = f;
        mprev = mnew;
        __syncthreads();   // all row-max reads done before overwrite with P

        // P = exp(S - mnew), each thread owns 32 cols of its row
#pragma unroll 8
        for (int c = 0; c < 32; c++) {
            int cc = sseg + c;
            Ps[srow * 65 + cc] = __expf(Ps[srow * 65 + cc] - mnew);
        }
        __syncthreads();

        // row sum -> online l update
        float rs = 0.f;
#pragma unroll 8
        for (int c = 0; c < 64; c++) rs += Ps[srow * 65 + c];
        lsum = lsum * f + rs;

        // PV: out[q][d] (q = ty*8+i, d = tx*4+j), rescale then accumulate
#pragma unroll
        for (int i = 0; i < 8; i++) {
            float fi = fac[ty * 8 + i];
#pragma unroll
            for (int j = 0; j < 4; j++) acc[i][j] *= fi;
        }
#pragma unroll 4
        for (int kk = 0; kk < KB; kk++) {
            float a[8];
#pragma unroll
            for (int i = 0; i < 8; i++) a[i] = Ps[(ty * 8 + i) * 65 + kk];
            float4 v4 = *(const float4*)(&Vs[kk * 64 + tx * 4]);
            float bb[4] = {v4.x, v4.y, v4.z, v4.w};
#pragma unroll
            for (int i = 0; i < 8; i++)
#pragma unroll
                for (int j = 0; j < 4; j++) acc[i][j] += a[i] * bb[j];
        }
    }

    __syncthreads();
    if (sseg == 0) fac[srow] = 1.0f / lsum;
    __syncthreads();

#pragma unroll
    for (int i = 0; i < 8; i++) {
        int q = q0 + ty * 8 + i;
        float inv = fac[ty * 8 + i];
        float4 o;
        o.x = acc[i][0] * inv; o.y = acc[i][1] * inv;
        o.z = acc[i][2] * inv; o.w = acc[i][3] * inv;
        *(float4*)(&g_ATT[((size_t)(b * Lq + q)) * Hdim + h * HD + tx * 4]) = o;
    }
}

// ---------------- residual + LayerNorm ---------------------------------------
__global__ __launch_bounds__(256) void ln_k(const float* __restrict__ X,
                                            const float* __restrict__ gamma,
                                            const float* __restrict__ beta,
                                            float* __restrict__ out)
{
    __shared__ float buf[Hdim];
    __shared__ float rs[8], rss[8], stats[2];
    const int m = blockIdx.x;
    const int tid = threadIdx.x;
    const int lane = tid & 31, wid = tid >> 5;

    float s = 0.f, ss = 0.f;
#pragma unroll
    for (int i = 0; i < 4; i++) {
        int hh = i * 256 + tid;
        float v = g_O[(size_t)m * Hdim + hh] + X[(size_t)m * Hdim + hh];
        buf[hh] = v;
        s += v; ss += v * v;
    }
#pragma unroll
    for (int o = 16; o > 0; o >>= 1) {
        s  += __shfl_xor_sync(0xffffffffu, s, o);
        ss += __shfl_xor_sync(0xffffffffu, ss, o);
    }
    if (lane == 0) { rs[wid] = s; rss[wid] = ss; }
    __syncthreads();
    if (tid == 0) {
        float S = 0.f, SS = 0.f;
#pragma unroll
        for (int i = 0; i < 8; i++) { S += rs[i]; SS += rss[i]; }
        float mu = S * (1.0f / Hdim);
        stats[0] = mu;
        stats[1] = rsqrtf(SS * (1.0f / Hdim) - mu * mu + 1e-12f);
    }
    __syncthreads();
    float mu = stats[0], r = stats[1];
#pragma unroll
    for (int i = 0; i < 4; i++) {
        int hh = i * 256 + tid;
        out[(size_t)m * Hdim + hh] = (buf[hh] - mu) * r * gamma[hh] + beta[hh];
    }
}

// ---------------- launch ------------------------------------------------------
extern "C" void kernel_launch(void* const* d_in, const int* in_sizes, int n_in,
                              void* d_out, int out_size)
{
    const float* X     = (const float*)d_in[0];
    const float* mask  = (const float*)d_in[1];
    const float* Wq    = (const float*)d_in[2];
    const float* bq    = (const float*)d_in[3];
    const float* Wk    = (const float*)d_in[4];
    const float* bk    = (const float*)d_in[5];
    const float* Wv    = (const float*)d_in[6];
    const float* bv    = (const float*)d_in[7];
    const float* Wo    = (const float*)d_in[8];
    const float* bo    = (const float*)d_in[9];
    const float* gamma = (const float*)d_in[10];
    const float* beta  = (const float*)d_in[11];

    cudaFuncSetAttribute(attn_k, cudaFuncAttributeMaxDynamicSharedMemorySize,
                         ATTN_SMEM_BYTES);

    dim3 gg(Hdim / TBN, MROWS / TBM);   // (8, 32)
    gemm_k<<<gg, 256>>>(X, Wq, bq, 0);
    gemm_k<<<gg, 256>>>(X, Wk, bk, 1);
    gemm_k<<<gg, 256>>>(X, Wv, bv, 2);

    attn_k<<<dim3(Lq / QB, NH, Bdim), 256, ATTN_SMEM_BYTES>>>(mask);

    gemm_k<<<gg, 256>>>(nullptr, Wo, bo, 3);

    ln_k<<<MROWS, 256>>>(X, gamma, beta, (float*)d_out);
}